// round 2
// baseline (speedup 1.0000x reference)
#include <cuda_runtime.h>
#include <math.h>
#include <stdint.h>

// ---------------------------------------------------------------------------
// Problem dims (fixed by the dataset)
// ---------------------------------------------------------------------------
#define NP 2048   // pairs
#define NX 4096   // X/Y rows
#define DX 768    // X dim
#define DY 512    // Y dim
#define DF 256    // feature dim
#define EPS_INV 20.0f   // 1/0.05
#define SINK_IT 10

// acc slots
#define S_MARG 0
#define S_SAIL 1
#define S_EXP  2
#define S_IMP  3
#define S_OT   4
#define S_N1   5
#define S_N2   6
#define S_DT   7
#define S_SQA  8
#define S_SQB  9
#define S_SQG  10

// ---------------------------------------------------------------------------
// Static device scratch (no allocations allowed)
// ---------------------------------------------------------------------------
__device__ float g_Mp[(size_t)NP * NP];        // cos/eps for pairs
__device__ float g_Mu[(size_t)NX * NX];        // cos/eps latent
__device__ float g_Ca[(size_t)NX * NX];        // anchor-space M
__device__ float g_P [(size_t)NX * NX];        // plan_u
__device__ float g_Xa[NX * DX];
__device__ float g_Ya[NX * DY];
__device__ float g_Xu[NX * DX];
__device__ float g_Yu[NX * DY];
__device__ float g_Xn[NX * DX];
__device__ float g_Yn[NX * DY];
__device__ float g_fXn[NX * DF];
__device__ float g_fYn[NX * DF];
__device__ float g_fXpn[NP * DF];
__device__ float g_fYpn[NP * DF];
__device__ float g_W[NX * DX];                 // reused scratch (X@Sxx, Y@Syy, Xs, Ys)
__device__ float g_T[NX * DY];                 // reused scratch (Xn@Sxy, P@Yu)
__device__ float g_Sxx[DX * DX];
__device__ float g_Syy[DY * DY];
__device__ float g_Sxy[DX * DY];
__device__ float g_Gxx[DX * DX];
__device__ float g_Gyy[DY * DY];
__device__ float g_Gfx[DF * DF];
__device__ float g_Gfy[DF * DF];
__device__ float g_Gxf[DX * DF];
__device__ float g_Gfyy[DF * DY];
__device__ float g_U1[DX * DY];
__device__ float g_V1[DX * DY];
__device__ float g_W1[DX * DY];
__device__ float g_Ag[DX * DX];
__device__ float g_Bg[DY * DY];
__device__ float g_Gg[DX * DY];
__device__ float g_up[NP], g_vp[NP];
__device__ float g_uu[NX], g_vu[NX];
__device__ float g_ua[NX], g_va[NX];
__device__ float g_arow[NX], g_bcol[NX];
__device__ float g_ap[NP], g_bp[NP];
__device__ float g_pm[16 * NX], g_ps[16 * NX];
__device__ double g_acc[16];

// ---------------------------------------------------------------------------
// Reduction helpers
// ---------------------------------------------------------------------------
__device__ __forceinline__ float warpSum(float v) {
    #pragma unroll
    for (int o = 16; o; o >>= 1) v += __shfl_xor_sync(0xffffffffu, v, o);
    return v;
}
__device__ __forceinline__ double warpSumD(double v) {
    #pragma unroll
    for (int o = 16; o; o >>= 1) v += __shfl_xor_sync(0xffffffffu, v, o);
    return v;
}
__device__ float blockSum(float v) {
    __shared__ float s[32];
    __syncthreads();
    int lane = threadIdx.x & 31, wid = threadIdx.x >> 5;
    v = warpSum(v);
    if (lane == 0) s[wid] = v;
    __syncthreads();
    if (wid == 0) {
        int nw = blockDim.x >> 5;
        v = (lane < nw) ? s[lane] : 0.f;
        v = warpSum(v);
    }
    return v;
}
__device__ double blockSumD(double v) {
    __shared__ double s[32];
    __syncthreads();
    int lane = threadIdx.x & 31, wid = threadIdx.x >> 5;
    v = warpSumD(v);
    if (lane == 0) s[wid] = v;
    __syncthreads();
    if (wid == 0) {
        int nw = blockDim.x >> 5;
        v = (lane < nw) ? s[lane] : 0.0;
        v = warpSumD(v);
    }
    return v;
}

__device__ __forceinline__ void lse_combine(float& m, float& s, float m2, float s2) {
    if (m2 == -INFINITY) return;
    if (m == -INFINITY) { m = m2; s = s2; return; }
    float mn = fmaxf(m, m2);
    s = s * expf(m - mn) + s2 * expf(m2 - mn);
    m = mn;
}
__device__ void blockLSE(float& m, float& s) {
    __shared__ float sm[32], ss[32];
    __syncthreads();
    int lane = threadIdx.x & 31, wid = threadIdx.x >> 5;
    #pragma unroll
    for (int o = 16; o; o >>= 1) {
        float m2 = __shfl_xor_sync(0xffffffffu, m, o);
        float s2 = __shfl_xor_sync(0xffffffffu, s, o);
        lse_combine(m, s, m2, s2);
    }
    if (lane == 0) { sm[wid] = m; ss[wid] = s; }
    __syncthreads();
    if (wid == 0) {
        int nw = blockDim.x >> 5;
        m = (lane < nw) ? sm[lane] : -INFINITY;
        s = (lane < nw) ? ss[lane] : 0.f;
        #pragma unroll
        for (int o = 16; o; o >>= 1) {
            float m2 = __shfl_xor_sync(0xffffffffu, m, o);
            float s2 = __shfl_xor_sync(0xffffffffu, s, o);
            lse_combine(m, s, m2, s2);
        }
    }
}

// ---------------------------------------------------------------------------
// GEMM: C[M,N] = alpha * sum_k opA(m,k)*opB(k,n)
// TA=0: A row-major MxK ; TA=1: A row-major KxM (use A^T)
// TB=0: B row-major KxN ; TB=1: B row-major NxK (use B^T)
// Requires: M,N % 128 == 0, K % 8 == 0, ld's % 4 == 0. 256 threads, 128x128 tile.
// ---------------------------------------------------------------------------
template <int TA, int TB>
__global__ void gemm_kernel(const float* __restrict__ A, const float* __restrict__ B,
                            float* __restrict__ C, int K,
                            int lda, int ldb, int ldc, float alpha) {
    __shared__ __align__(16) float As[8][128];
    __shared__ __align__(16) float Bs[8][128];
    const int tid = threadIdx.x;
    const int bm = blockIdx.y * 128;
    const int bn = blockIdx.x * 128;
    const int tx = tid & 15, ty = tid >> 4;

    float acc[8][8];
    #pragma unroll
    for (int i = 0; i < 8; i++)
        #pragma unroll
        for (int j = 0; j < 8; j++) acc[i][j] = 0.f;

    for (int k0 = 0; k0 < K; k0 += 8) {
        if (TA == 0) {
            int m = tid >> 1;
            int k = (tid & 1) * 4;
            float4 a = *(const float4*)&A[(size_t)(bm + m) * lda + k0 + k];
            As[k + 0][m] = a.x; As[k + 1][m] = a.y; As[k + 2][m] = a.z; As[k + 3][m] = a.w;
        } else {
            int k = tid >> 5;
            int m = (tid & 31) * 4;
            float4 a = *(const float4*)&A[(size_t)(k0 + k) * lda + bm + m];
            *(float4*)&As[k][m] = a;
        }
        if (TB == 0) {
            int k = tid >> 5;
            int n = (tid & 31) * 4;
            float4 b = *(const float4*)&B[(size_t)(k0 + k) * ldb + bn + n];
            *(float4*)&Bs[k][n] = b;
        } else {
            int n = tid >> 1;
            int k = (tid & 1) * 4;
            float4 b = *(const float4*)&B[(size_t)(bn + n) * ldb + k0 + k];
            Bs[k + 0][n] = b.x; Bs[k + 1][n] = b.y; Bs[k + 2][n] = b.z; Bs[k + 3][n] = b.w;
        }
        __syncthreads();
        #pragma unroll
        for (int k = 0; k < 8; k++) {
            float4 a0 = *(const float4*)&As[k][ty * 8];
            float4 a1 = *(const float4*)&As[k][ty * 8 + 4];
            float4 b0 = *(const float4*)&Bs[k][tx * 8];
            float4 b1 = *(const float4*)&Bs[k][tx * 8 + 4];
            float ra[8] = {a0.x, a0.y, a0.z, a0.w, a1.x, a1.y, a1.z, a1.w};
            float rb[8] = {b0.x, b0.y, b0.z, b0.w, b1.x, b1.y, b1.z, b1.w};
            #pragma unroll
            for (int i = 0; i < 8; i++)
                #pragma unroll
                for (int j = 0; j < 8; j++)
                    acc[i][j] = fmaf(ra[i], rb[j], acc[i][j]);
        }
        __syncthreads();
    }
    #pragma unroll
    for (int i = 0; i < 8; i++) {
        int m = bm + ty * 8 + i;
        #pragma unroll
        for (int j = 0; j < 8; j += 4) {
            float4 o;
            o.x = alpha * acc[i][j + 0];
            o.y = alpha * acc[i][j + 1];
            o.z = alpha * acc[i][j + 2];
            o.w = alpha * acc[i][j + 3];
            *(float4*)&C[(size_t)m * ldc + bn + tx * 8 + j] = o;
        }
    }
}

// ---------------------------------------------------------------------------
// Elementwise / reduction kernels
// ---------------------------------------------------------------------------
__global__ void zero_acc_kernel(double* a) { if (threadIdx.x < 16) a[threadIdx.x] = 0.0; }
__global__ void zero_vec_kernel(float* p, int n) {
    int i = blockIdx.x * blockDim.x + threadIdx.x;
    if (i < n) p[i] = 0.f;
}

// out = row-normalized in (L2, clamped at 1e-8)
__global__ void rownorm_kernel(const float* __restrict__ in, float* __restrict__ out, int D) {
    int row = blockIdx.x;
    const float* r = in + (size_t)row * D;
    float ss = 0.f;
    for (int i = threadIdx.x; i < D; i += blockDim.x) { float v = r[i]; ss += v * v; }
    ss = blockSum(ss);
    __shared__ float s_inv;
    if (threadIdx.x == 0) s_inv = 1.f / fmaxf(sqrtf(ss), 1e-8f);
    __syncthreads();
    float inv = s_inv;
    for (int i = threadIdx.x; i < D; i += blockDim.x) out[(size_t)row * D + i] = r[i] * inv;
}

// out = X / clamp(sqrt(sum(X*W, -1)), 1e-8)   (anchor Mahalanobis-ish norm)
__global__ void quadnorm_kernel(const float* __restrict__ X, const float* __restrict__ W,
                                float* __restrict__ out, int D) {
    int row = blockIdx.x;
    const float* xr = X + (size_t)row * D;
    const float* wr = W + (size_t)row * D;
    float ss = 0.f;
    for (int i = threadIdx.x; i < D; i += blockDim.x) ss += xr[i] * wr[i];
    ss = blockSum(ss);
    __shared__ float s_inv;
    if (threadIdx.x == 0) s_inv = 1.f / fmaxf(sqrtf(ss), 1e-8f);
    __syncthreads();
    float inv = s_inv;
    for (int i = threadIdx.x; i < D; i += blockDim.x) out[(size_t)row * D + i] = xr[i] * inv;
}

__global__ void scale_rows_sqrt_kernel(const float* __restrict__ X, const float* __restrict__ a,
                                       float* __restrict__ out, int D) {
    int row = blockIdx.x;
    float sc = sqrtf(fmaxf(a[row], 0.f));
    for (int i = threadIdx.x; i < D; i += blockDim.x)
        out[(size_t)row * D + i] = X[(size_t)row * D + i] * sc;
}

// u[row] = log_a - LSE_c(M[row,c] + v[c])
__global__ void row_lse_kernel(const float* __restrict__ M, const float* __restrict__ v,
                               float* __restrict__ u, int ny, float log_a) {
    int row = blockIdx.x;
    const float* Mr = M + (size_t)row * ny;
    float m = -INFINITY, s = 0.f;
    for (int c = threadIdx.x; c < ny; c += blockDim.x) {
        float x = Mr[c] + v[c];
        float mn = fmaxf(m, x);
        s = s * expf(m - mn) + expf(x - mn);
        m = mn;
    }
    blockLSE(m, s);
    if (threadIdx.x == 0) u[row] = log_a - (m + logf(s));
}

__global__ void col_lse_partial_kernel(const float* __restrict__ M, const float* __restrict__ u,
                                       float* __restrict__ pm, float* __restrict__ ps,
                                       int nx, int ny, int chunk) {
    int col = blockIdx.x * blockDim.x + threadIdx.x;
    int r0 = blockIdx.y * chunk;
    int r1 = min(r0 + chunk, nx);
    float m = -INFINITY, s = 0.f;
    for (int r = r0; r < r1; r++) {
        float x = M[(size_t)r * ny + col] + __ldg(&u[r]);
        float mn = fmaxf(m, x);
        s = s * expf(m - mn) + expf(x - mn);
        m = mn;
    }
    pm[(size_t)blockIdx.y * ny + col] = m;
    ps[(size_t)blockIdx.y * ny + col] = s;
}

__global__ void col_lse_combine_kernel(const float* __restrict__ pm, const float* __restrict__ ps,
                                       float* __restrict__ v, int ny, int nch, float log_b) {
    int col = blockIdx.x * blockDim.x + threadIdx.x;
    float m = -INFINITY, s = 0.f;
    for (int c = 0; c < nch; c++)
        lse_combine(m, s, pm[(size_t)c * ny + col], ps[(size_t)c * ny + col]);
    v[col] = log_b - (m + logf(s));
}

// rowsum of exp(M+u+v); optionally writes the plan to P
__global__ void plan_rowsum_kernel(const float* __restrict__ M, const float* __restrict__ u,
                                   const float* __restrict__ v, float* __restrict__ rowsum,
                                   float* __restrict__ P, int ny) {
    int row = blockIdx.x;
    float uv = u[row];
    const float* Mr = M + (size_t)row * ny;
    float s = 0.f;
    for (int c = threadIdx.x; c < ny; c += blockDim.x) {
        float p = expf(Mr[c] + uv + v[c]);
        if (P) P[(size_t)row * ny + c] = p;
        s += p;
    }
    s = blockSum(s);
    if (threadIdx.x == 0) rowsum[row] = s;
}

__global__ void plan_colsum_partial_kernel(const float* __restrict__ M, const float* __restrict__ u,
                                           const float* __restrict__ v, float* __restrict__ ps,
                                           int nx, int ny, int chunk) {
    int col = blockIdx.x * blockDim.x + threadIdx.x;
    int r0 = blockIdx.y * chunk;
    int r1 = min(r0 + chunk, nx);
    float vc = v[col];
    float s = 0.f;
    for (int r = r0; r < r1; r++)
        s += expf(M[(size_t)r * ny + col] + __ldg(&u[r]) + vc);
    ps[(size_t)blockIdx.y * ny + col] = s;
}

__global__ void colsum_combine_kernel(const float* __restrict__ ps, float* __restrict__ b,
                                      int ny, int nch) {
    int col = blockIdx.x * blockDim.x + threadIdx.x;
    float s = 0.f;
    for (int c = 0; c < nch; c++) s += ps[(size_t)c * ny + col];
    b[col] = s;
}

// sum (sums[i] - 1/n)^2 -> acc[S_MARG]
__global__ void marg_acc_kernel(const float* __restrict__ sums, int n, double* acc) {
    int i = blockIdx.x * blockDim.x + threadIdx.x;
    double t = 0.0;
    if (i < n) {
        float d = sums[i] - 1.f / (float)n;
        t = (double)d * (double)d;
    }
    t = blockSumD(t);
    if (threadIdx.x == 0) atomicAdd(&acc[S_MARG], t);
}

// SAIL: sum softplus(-z), z = Mp*0.5*target
__global__ void sail_acc_kernel(const float* __restrict__ Mp, int n, double* acc) {
    size_t total = (size_t)n * n;
    double t = 0.0;
    for (size_t idx = (size_t)blockIdx.x * blockDim.x + threadIdx.x; idx < total;
         idx += (size_t)gridDim.x * blockDim.x) {
        int i = (int)(idx / n), j = (int)(idx - (size_t)i * n);
        float z = Mp[idx] * 0.5f;
        if (i != j) z = -z;
        float a = -z;
        float sp = fmaxf(a, 0.f) + log1pf(expf(-fabsf(a)));
        t += (double)sp;
    }
    t = blockSumD(t);
    if (threadIdx.x == 0) atomicAdd(&acc[S_SAIL], t);
}

// diag terms: IMP += logp_ii + logN ; EXP += (1 - cos_ii)/2
__global__ void diag_acc_kernel(const float* __restrict__ Mp, const float* __restrict__ u,
                                const float* __restrict__ v, int n, float logN, double* acc) {
    int i = blockIdx.x * blockDim.x + threadIdx.x;
    double ti = 0.0, te = 0.0;
    if (i < n) {
        float mii = Mp[(size_t)i * n + i];
        ti = (double)(mii + u[i] + v[i] + logN);
        te = (double)((1.f - mii * 0.05f) * 0.5f);
    }
    ti = blockSumD(ti);
    __shared__ double sh;
    if (threadIdx.x == 0) sh = ti;
    te = blockSumD(te);
    if (threadIdx.x == 0) {
        atomicAdd(&acc[S_IMP], sh);
        atomicAdd(&acc[S_EXP], te);
    }
}

// L_ot = sum exp(la) * (la - lu)
__global__ void ot_acc_kernel(const float* __restrict__ Ca, const float* __restrict__ Mu,
                              const float* __restrict__ ua, const float* __restrict__ va,
                              const float* __restrict__ uu, const float* __restrict__ vu,
                              int n, double* acc) {
    size_t total = (size_t)n * n;
    double t = 0.0;
    for (size_t idx = (size_t)blockIdx.x * blockDim.x + threadIdx.x; idx < total;
         idx += (size_t)gridDim.x * blockDim.x) {
        int i = (int)(idx / n), j = (int)(idx - (size_t)i * n);
        float la = Ca[idx] + ua[i] + va[j];
        float lu = Mu[idx] + uu[i] + vu[j];
        t += (double)(expf(la) * (la - lu));
    }
    t = blockSumD(t);
    if (threadIdx.x == 0) atomicAdd(&acc[S_OT], t);
}

__global__ void dot_acc_kernel(const float* __restrict__ A, const float* __restrict__ B,
                               int n, double* acc, int slot) {
    double t = 0.0;
    for (int i = blockIdx.x * blockDim.x + threadIdx.x; i < n; i += gridDim.x * blockDim.x)
        t += (double)A[i] * (double)B[i];
    t = blockSumD(t);
    if (threadIdx.x == 0) atomicAdd(&acc[slot], t);
}

__global__ void sumsq_acc_kernel(const float* __restrict__ A, int n, double* acc, int slot) {
    double t = 0.0;
    for (int i = blockIdx.x * blockDim.x + threadIdx.x; i < n; i += gridDim.x * blockDim.x)
        t += (double)A[i] * (double)A[i];
    t = blockSumD(t);
    if (threadIdx.x == 0) atomicAdd(&acc[slot], t);
}

__global__ void finalize_kernel(const double* __restrict__ acc, float* __restrict__ out) {
    double L = acc[S_MARG]
             + acc[S_SAIL] / ((double)NP * (double)NP)
             + acc[S_EXP] / (double)NP
             - acc[S_IMP] / (double)NP
             + acc[S_OT]
             + (acc[S_N1] + acc[S_N2] - 2.0 * acc[S_DT]) / ((double)NX * (double)NX)
             + (acc[S_SQA] + acc[S_SQB] - 2.0 * acc[S_SQG]);
    out[0] = (float)L;
}

// ---------------------------------------------------------------------------
// Host side
// ---------------------------------------------------------------------------
static inline void launch_gemm(int TA, int TB, const float* A, const float* B, float* C,
                               int M, int N, int K, int lda, int ldb, int ldc, float alpha) {
    dim3 grid(N / 128, M / 128), block(256);
    if (TA == 0 && TB == 0) gemm_kernel<0, 0><<<grid, block>>>(A, B, C, K, lda, ldb, ldc, alpha);
    else if (TA == 0 && TB == 1) gemm_kernel<0, 1><<<grid, block>>>(A, B, C, K, lda, ldb, ldc, alpha);
    else gemm_kernel<1, 0><<<grid, block>>>(A, B, C, K, lda, ldb, ldc, alpha);
}

static void run_sinkhorn(float* M, float* u, float* v, int nx, int ny, float* pm, float* ps) {
    float log_a = -logf((float)nx), log_b = -logf((float)ny);
    const int CH = 256;
    int nch = nx / CH;
    zero_vec_kernel<<<(ny + 255) / 256, 256>>>(v, ny);
    dim3 cgrid(ny / 256, nch);
    for (int it = 0; it < SINK_IT; it++) {
        row_lse_kernel<<<nx, 256>>>(M, v, u, ny, log_a);
        col_lse_partial_kernel<<<cgrid, 256>>>(M, u, pm, ps, nx, ny, CH);
        col_lse_combine_kernel<<<ny / 256, 256>>>(pm, ps, v, ny, nch, log_b);
    }
}

#define GETSYM(ptr, sym) do { void* _t; cudaGetSymbolAddress(&_t, sym); ptr = (float*)_t; } while (0)

extern "C" void kernel_launch(void* const* d_in, const int* in_sizes, int n_in,
                              void* d_out, int out_size) {
    const float* fXp = (const float*)d_in[0];   // 2048x256
    const float* fYp = (const float*)d_in[1];   // 2048x256
    const float* X   = (const float*)d_in[2];   // 4096x768
    const float* Y   = (const float*)d_in[3];   // 4096x512
    const float* fX  = (const float*)d_in[4];   // 4096x256
    const float* fY  = (const float*)d_in[5];   // 4096x256
    const float* Xan = (const float*)d_in[6];   // 4096x768
    const float* Yan = (const float*)d_in[7];   // 4096x512
    float* out = (float*)d_out;

    float *Mp, *Mu, *Ca, *P, *Xa, *Ya, *Xu, *Yu, *Xn, *Yn, *fXn, *fYn, *fXpn, *fYpn;
    float *W, *T, *Sxx, *Syy, *Sxy, *Gxx, *Gyy, *Gfx, *Gfy, *Gxf, *Gfyy, *U1, *V1, *W1;
    float *Ag, *Bg, *Gg, *up, *vp, *uu, *vu, *ua, *va, *arow, *bcol, *ap, *bp, *pm, *ps;
    double* acc;
    GETSYM(Mp, g_Mp); GETSYM(Mu, g_Mu); GETSYM(Ca, g_Ca); GETSYM(P, g_P);
    GETSYM(Xa, g_Xa); GETSYM(Ya, g_Ya); GETSYM(Xu, g_Xu); GETSYM(Yu, g_Yu);
    GETSYM(Xn, g_Xn); GETSYM(Yn, g_Yn); GETSYM(fXn, g_fXn); GETSYM(fYn, g_fYn);
    GETSYM(fXpn, g_fXpn); GETSYM(fYpn, g_fYpn);
    GETSYM(W, g_W); GETSYM(T, g_T);
    GETSYM(Sxx, g_Sxx); GETSYM(Syy, g_Syy); GETSYM(Sxy, g_Sxy);
    GETSYM(Gxx, g_Gxx); GETSYM(Gyy, g_Gyy); GETSYM(Gfx, g_Gfx); GETSYM(Gfy, g_Gfy);
    GETSYM(Gxf, g_Gxf); GETSYM(Gfyy, g_Gfyy); GETSYM(U1, g_U1); GETSYM(V1, g_V1); GETSYM(W1, g_W1);
    GETSYM(Ag, g_Ag); GETSYM(Bg, g_Bg); GETSYM(Gg, g_Gg);
    GETSYM(up, g_up); GETSYM(vp, g_vp); GETSYM(uu, g_uu); GETSYM(vu, g_vu);
    GETSYM(ua, g_ua); GETSYM(va, g_va);
    GETSYM(arow, g_arow); GETSYM(bcol, g_bcol); GETSYM(ap, g_ap); GETSYM(bp, g_bp);
    GETSYM(pm, g_pm); GETSYM(ps, g_ps);
    { void* _t; cudaGetSymbolAddress(&_t, g_acc); acc = (double*)_t; }

    zero_acc_kernel<<<1, 32>>>(acc);

    // --- row norms ---
    rownorm_kernel<<<NX, 256>>>(Xan, Xa, DX);
    rownorm_kernel<<<NX, 256>>>(Yan, Ya, DY);
    rownorm_kernel<<<NP, 256>>>(fXp, fXpn, DF);
    rownorm_kernel<<<NP, 256>>>(fYp, fYpn, DF);
    rownorm_kernel<<<NX, 256>>>(fX, fXn, DF);
    rownorm_kernel<<<NX, 256>>>(fY, fYn, DF);
    rownorm_kernel<<<NX, 256>>>(X, Xu, DX);
    rownorm_kernel<<<NX, 256>>>(Y, Yu, DY);

    // --- anchor covariances ---
    launch_gemm(1, 0, Xa, Xa, Sxx, DX, DX, NX, DX, DX, DX, 1.f / NX);
    launch_gemm(1, 0, Ya, Ya, Syy, DY, DY, NX, DY, DY, DY, 1.f / NX);
    launch_gemm(1, 0, Xa, Ya, Sxy, DX, DY, NX, DX, DY, DY, 1.f / NX);

    // --- cosine/eps matrices ---
    launch_gemm(0, 1, fXpn, fYpn, Mp, NP, NP, DF, DF, DF, NP, EPS_INV);
    launch_gemm(0, 1, fXn, fYn, Mu, NX, NX, DF, DF, DF, NX, EPS_INV);

    // --- shared-space sinkhorns ---
    run_sinkhorn(Mp, up, vp, NP, NP, pm, ps);
    run_sinkhorn(Mu, uu, vu, NX, NX, pm, ps);

    // --- pairs plan stats: marginals + SAIL + diag losses ---
    plan_rowsum_kernel<<<NP, 256>>>(Mp, up, vp, ap, nullptr, NP);
    plan_colsum_partial_kernel<<<dim3(NP / 256, NP / 256), 256>>>(Mp, up, vp, ps, NP, NP, 256);
    colsum_combine_kernel<<<NP / 256, 256>>>(ps, bp, NP, NP / 256);
    marg_acc_kernel<<<NP / 256, 256>>>(ap, NP, acc);
    marg_acc_kernel<<<NP / 256, 256>>>(bp, NP, acc);
    sail_acc_kernel<<<1024, 256>>>(Mp, NP, acc);
    diag_acc_kernel<<<NP / 256, 256>>>(Mp, up, vp, NP, logf((float)NP), acc);

    // --- latent plan stats (and materialize plan_u) ---
    plan_rowsum_kernel<<<NX, 256>>>(Mu, uu, vu, arow, P, NX);
    plan_colsum_partial_kernel<<<dim3(NX / 256, NX / 256), 256>>>(Mu, uu, vu, ps, NX, NX, 256);
    colsum_combine_kernel<<<NX / 256, 256>>>(ps, bcol, NX, NX / 256);
    marg_acc_kernel<<<NX / 256, 256>>>(arow, NX, acc);
    marg_acc_kernel<<<NX / 256, 256>>>(bcol, NX, acc);

    // --- anchor-space normalization + plan ---
    launch_gemm(0, 0, X, Sxx, W, NX, DX, DX, DX, DX, DX, 1.f);
    quadnorm_kernel<<<NX, 256>>>(X, W, Xn, DX);
    launch_gemm(0, 0, Y, Syy, W, NX, DY, DY, DY, DY, DY, 1.f);
    quadnorm_kernel<<<NX, 256>>>(Y, W, Yn, DY);
    launch_gemm(0, 0, Xn, Sxy, T, NX, DY, DX, DX, DY, DY, 1.f);
    launch_gemm(0, 1, T, Yn, Ca, NX, NX, DY, DY, DY, NX, EPS_INV);
    run_sinkhorn(Ca, ua, va, NX, NX, pm, ps);

    // --- L_ot ---
    ot_acc_kernel<<<2048, 256>>>(Ca, Mu, ua, va, uu, vu, NX, acc);

    // --- L_div ---
    launch_gemm(1, 0, Xn, Xn, Gxx, DX, DX, NX, DX, DX, DX, 1.f);
    launch_gemm(1, 0, Yn, Yn, Gyy, DY, DY, NX, DY, DY, DY, 1.f);
    launch_gemm(1, 0, fXn, fXn, Gfx, DF, DF, NX, DF, DF, DF, 1.f);
    launch_gemm(1, 0, fYn, fYn, Gfy, DF, DF, NX, DF, DF, DF, 1.f);
    launch_gemm(1, 0, Xn, fXn, Gxf, DX, DF, NX, DX, DF, DF, 1.f);
    launch_gemm(1, 0, fYn, Yn, Gfyy, DF, DY, NX, DF, DY, DY, 1.f);
    launch_gemm(0, 0, Gxx, Sxy, U1, DX, DY, DX, DX, DY, DY, 1.f);
    launch_gemm(0, 0, U1, Gyy, V1, DX, DY, DY, DY, DY, DY, 1.f);
    launch_gemm(0, 0, Gxf, Gfyy, W1, DX, DY, DF, DF, DY, DY, 1.f);
    dot_acc_kernel<<<256, 256>>>(V1, Sxy, DX * DY, acc, S_N1);
    dot_acc_kernel<<<256, 256>>>(Gfx, Gfy, DF * DF, acc, S_N2);
    dot_acc_kernel<<<256, 256>>>(W1, Sxy, DX * DY, acc, S_DT);

    // --- L_gw ---
    scale_rows_sqrt_kernel<<<NX, 256>>>(Xu, arow, W, DX);
    launch_gemm(1, 0, W, W, Ag, DX, DX, NX, DX, DX, DX, 1.f);
    sumsq_acc_kernel<<<256, 256>>>(Ag, DX * DX, acc, S_SQA);
    scale_rows_sqrt_kernel<<<NX, 256>>>(Yu, bcol, W, DY);
    launch_gemm(1, 0, W, W, Bg, DY, DY, NX, DY, DY, DY, 1.f);
    sumsq_acc_kernel<<<256, 256>>>(Bg, DY * DY, acc, S_SQB);
    launch_gemm(0, 0, P, Yu, T, NX, DY, NX, NX, DY, DY, 1.f);   // PY = plan_u @ Yu
    launch_gemm(1, 0, Xu, T, Gg, DX, DY, NX, DX, DY, DY, 1.f);  // G = Xu^T @ PY
    sumsq_acc_kernel<<<256, 256>>>(Gg, DX * DY, acc, S_SQG);

    finalize_kernel<<<1, 1>>>(acc, out);
}